// round 8
// baseline (speedup 1.0000x reference)
#include <cuda_runtime.h>
#include <cstdint>

// Embedding gather: out[i, :] = table[indices[i], :]
// indices: int32[4194304], table: float32[1000000, 16], out: float32[4194304, 16]
//
// Journal: R4 (2 threads/row, v8 loads) = 77.9us @ 5252 GB/s. R6 proved L2
// evict_last pinning is dead on this part. R7 proved aggressive per-thread
// MLP batching (grid-stride x4) regresses via L1tex queue contention.
//
// This round: one thread per ROW. 1 index load (no duplicate read per row),
// then 2 independent v8 loads covering the row's 64 B (same cacheline -> no
// added DRAM randomness, gentle MLP=2), then 4 coalesced 128-bit streaming
// stores. Front-batched wavefronts per thread: 5 (vs R7's 12) -> below the
// L1tex contention regime.

struct __align__(32) f8 { float4 a, b; };

__device__ __forceinline__ f8 ldg_nc_f8(const f8* p) {
    f8 v;
    asm volatile(
        "ld.global.nc.v8.f32 {%0,%1,%2,%3,%4,%5,%6,%7}, [%8];"
        : "=f"(v.a.x), "=f"(v.a.y), "=f"(v.a.z), "=f"(v.a.w),
          "=f"(v.b.x), "=f"(v.b.y), "=f"(v.b.z), "=f"(v.b.w)
        : "l"(p));
    return v;
}

__global__ void __launch_bounds__(256) gather_kernel(
    const int* __restrict__ indices,
    const f8* __restrict__ table8,     // table as 32 B chunks: 2 per row
    float4* __restrict__ out4,
    int num_indices)
{
    int row = blockIdx.x * blockDim.x + threadIdx.x;
    if (row >= num_indices) return;

    long long idx = (long long)__ldcs(&indices[row]);

    // Two independent 256-bit loads covering the 64 B row (one cacheline).
    f8 v0 = ldg_nc_f8(&table8[idx * 2 + 0]);
    f8 v1 = ldg_nc_f8(&table8[idx * 2 + 1]);

    // 4 coalesced 128-bit streaming stores (64 B per thread, contiguous
    // across the warp -> perfect 2 KB warp store).
    float4* o = &out4[(long long)row * 4];
    __stcs(&o[0], v0.a);
    __stcs(&o[1], v0.b);
    __stcs(&o[2], v1.a);
    __stcs(&o[3], v1.b);
}

extern "C" void kernel_launch(void* const* d_in, const int* in_sizes, int n_in,
                              void* d_out, int out_size)
{
    // Resolve input order by size: indices = 4,194,304 elems, table = 16,000,000.
    int idx_slot = 0, tab_slot = 1;
    if (n_in >= 2 && in_sizes[0] > in_sizes[1]) { idx_slot = 1; tab_slot = 0; }

    const int* indices = (const int*)d_in[idx_slot];
    const f8*  table8  = (const f8*)d_in[tab_slot];
    float4*    out4    = (float4*)d_out;

    int num_indices = in_sizes[idx_slot];   // 4,194,304

    int threads = 256;
    int blocks = (num_indices + threads - 1) / threads;   // 16384
    gather_kernel<<<blocks, threads>>>(indices, table8, out4, num_indices);
}